// round 13
// baseline (speedup 1.0000x reference)
#include <cuda_runtime.h>

#define HH 1024
#define WW 1024
#define NB 32
#define HW (HH*WW)

constexpr int TOX = 116;   // output tile width
constexpr int TOY = 84;    // output tile height
constexpr int RW  = 130;   // region cols (logical 0..129)
constexpr int RH  = 98;    // region rows (0..97)
constexpr int SPW = 136;   // smem row stride (floats)
constexpr int NW  = 12;    // warps
constexpr int NTH = 384;
constexpr int GX  = 9;     // ceil(1024/116)
constexpr int GY  = 13;    // ceil(1024/84)
constexpr int SMEMB = 2 * RH * SPW * 4;   // 106624 B -> 2 CTAs/SM

// ---- convA weights ----
#define A00 0.2538f
#define A01 0.5022f
#define A02 0.07344f
#define A10 0.17864f
#define A11 1.0622f
#define A12 0.24616f
#define A20 0.2454f
#define A21 0.90548f
#define A22 0.52616f
#define BIASX (-0.07002f)
// ---- convB weights ----
#define B00 (-0.083f)
#define B01 (-3.15852f)
#define B02 (3.24172f)
#define B10 (-2.0894f)
#define B11 (-9.34624f)
#define B12 (-2.0018f)
#define B20 (6.889f)
#define B21 (-1.53384f)
#define B22 (7.71856f)

constexpr double SUMA_D =
    0.2538 + 0.5022 + 0.07344 + 0.17864 + 1.0622 + 0.24616 +
    0.2454 + 0.90548 + 0.52616;
constexpr double SUMB_D =
    -0.083 - 3.15852 + 3.24172 - 2.0894 - 9.34624 - 2.0018 +
    6.889 - 1.53384 + 7.71856;
constexpr float K0C = (float)(0.5 * (1.0 - SUMA_D + (double)BIASX));
constexpr float S2K = (float)(0.5 * SUMA_D);     // convA(const 0.5 field)

// ---- scratch ----
__device__ float g_bu2[(size_t)NB * HW];
__device__ float g_sA[(size_t)NB * HW];
__device__ float g_sB[(size_t)NB * HW];
__device__ unsigned g_kmin, g_kmax;

__device__ __forceinline__ unsigned encf(float f) {
    unsigned b = __float_as_uint(f);
    return (b & 0x80000000u) ? ~b : (b | 0x80000000u);
}
__device__ __forceinline__ float decf(unsigned u) {
    return (u & 0x80000000u) ? __uint_as_float(u & 0x7FFFFFFFu)
                             : __uint_as_float(~u);
}

__global__ void k_init() { g_kmin = 0xFFFFFFFFu; g_kmax = 0u; }

__global__ void k_minmax(const float4* __restrict__ x, int n4) {
    float mn = 3.4e38f, mx = -3.4e38f;
    for (int i = blockIdx.x * blockDim.x + threadIdx.x; i < n4;
         i += gridDim.x * blockDim.x) {
        float4 v = x[i];
        mn = fminf(mn, fminf(fminf(v.x, v.y), fminf(v.z, v.w)));
        mx = fmaxf(mx, fmaxf(fmaxf(v.x, v.y), fmaxf(v.z, v.w)));
    }
#pragma unroll
    for (int o = 16; o; o >>= 1) {
        mn = fminf(mn, __shfl_xor_sync(0xFFFFFFFFu, mn, o));
        mx = fmaxf(mx, __shfl_xor_sync(0xFFFFFFFFu, mx, o));
    }
    __shared__ float smn[8], smx[8];
    int w = threadIdx.x >> 5, l = threadIdx.x & 31;
    if (!l) { smn[w] = mn; smx[w] = mx; }
    __syncthreads();
    if (!w) {
        mn = (l < 8) ? smn[l] : 3.4e38f;
        mx = (l < 8) ? smx[l] : -3.4e38f;
#pragma unroll
        for (int o = 4; o; o >>= 1) {
            mn = fminf(mn, __shfl_xor_sync(0xFFFFFFFFu, mn, o));
            mx = fmaxf(mx, __shfl_xor_sync(0xFFFFFFFFu, mx, o));
        }
        if (!l) {
            atomicMin(&g_kmin, encf(mn));
            atomicMax(&g_kmax, encf(mx));
        }
    }
}

struct R6 { float v0, v1, v2, v3, v4, v5; };

template <int K, int M>   // M=0: A weights, M=1: B weights
__device__ __forceinline__ void frow(const R6& r, float4& a) {
    constexpr float w0 = M ? ((K==0)?B00:(K==1)?B10:B20) : ((K==0)?A00:(K==1)?A10:A20);
    constexpr float w1 = M ? ((K==0)?B01:(K==1)?B11:B21) : ((K==0)?A01:(K==1)?A11:A21);
    constexpr float w2 = M ? ((K==0)?B02:(K==1)?B12:B22) : ((K==0)?A02:(K==1)?A12:A22);
    a.x = fmaf(r.v0, w0, a.x); a.x = fmaf(r.v1, w1, a.x); a.x = fmaf(r.v2, w2, a.x);
    a.y = fmaf(r.v1, w0, a.y); a.y = fmaf(r.v2, w1, a.y); a.y = fmaf(r.v3, w2, a.y);
    a.z = fmaf(r.v2, w0, a.z); a.z = fmaf(r.v3, w1, a.z); a.z = fmaf(r.v4, w2, a.z);
    a.w = fmaf(r.v3, w0, a.w); a.w = fmaf(r.v4, w1, a.w); a.w = fmaf(r.v5, w2, a.w);
}

// Final row-2 contribution with the clamp folded into the last FMA.
// 0f3F06B26C is the IEEE-754 encoding of 0.52616f (A22); PTX hex-float literal
// keeps it out of the register file (regs are at the 2-CTA cap of 80).
#define SATFMA(acc, v)                                                    \
    asm("fma.rn.sat.f32 %0, %1, 0f3F06B26C, %0;" : "+f"(acc) : "f"(v))

__device__ __forceinline__ void frowZsat(const R6& r, float4& a) {
    a.x = fmaf(r.v0, A20, a.x); a.x = fmaf(r.v1, A21, a.x); SATFMA(a.x, r.v2);
    a.y = fmaf(r.v1, A20, a.y); a.y = fmaf(r.v2, A21, a.y); SATFMA(a.y, r.v3);
    a.z = fmaf(r.v2, A20, a.z); a.z = fmaf(r.v3, A21, a.z); SATFMA(a.z, r.v4);
    a.w = fmaf(r.v3, A20, a.w); a.w = fmaf(r.v4, A21, a.w); SATFMA(a.w, r.v5);
}

// BU2 = 0.5*convB(xn) + K0C ; xn = x*a2 + beta ; zero-pad in xn domain
// 2 output rows per thread: rows y0, y0+1 share the middle input rows.
__global__ void k_bu(const float* __restrict__ x) {
    int t = threadIdx.x;            // 0..255
    int y0 = blockIdx.y * 2;        // rows y0, y0+1
    int img = blockIdx.z;
    int c0 = 4 * t;
    float mn = decf(g_kmin), mx = decf(g_kmax);
    float a2 = 2.0f / (mx - mn);
    float beta = fmaf(-mn, a2, -1.0f);
    const float* xi = x + (size_t)img * HW;
    float* bo = g_bu2 + (size_t)img * HW;

    bool interior = (t >= 1) & (t <= 254) & (y0 >= 2) & (y0 <= 1020);
    if (interior) {
        R6 r[4];
#pragma unroll
        for (int j = 0; j < 4; j++) {
            const float* rp = xi + (size_t)(y0 - 1 + j) * WW + c0;
            float4 m = __ldg((const float4*)rp);
            r[j].v0 = __ldg(rp - 1);
            r[j].v1 = m.x; r[j].v2 = m.y; r[j].v3 = m.z; r[j].v4 = m.w;
            r[j].v5 = __ldg(rp + 4);
        }
        float4 accT = make_float4(0.f, 0.f, 0.f, 0.f);
        float4 accB = make_float4(0.f, 0.f, 0.f, 0.f);
        frow<0, 1>(r[0], accT); frow<1, 1>(r[1], accT); frow<2, 1>(r[2], accT);
        frow<0, 1>(r[1], accB); frow<1, 1>(r[2], accB); frow<2, 1>(r[3], accB);
        float C2 = fmaf(0.5f * beta, (float)SUMB_D, K0C);
        float h = 0.5f * a2;
        *(float4*)(bo + (size_t)y0 * WW + c0) = make_float4(
            fmaf(h, accT.x, C2), fmaf(h, accT.y, C2),
            fmaf(h, accT.z, C2), fmaf(h, accT.w, C2));
        *(float4*)(bo + (size_t)(y0 + 1) * WW + c0) = make_float4(
            fmaf(h, accB.x, C2), fmaf(h, accB.y, C2),
            fmaf(h, accB.z, C2), fmaf(h, accB.w, C2));
    } else {
#pragma unroll
        for (int rr = 0; rr < 2; rr++) {
            int y = y0 + rr;
#pragma unroll
            for (int i = 0; i < 4; i++) {
                int gx = c0 + i;
                float acc = 0.f;
#define T(dy, dx, w)                                                   \
                {                                                      \
                    int yy = y + (dy), xx = gx + (dx);                 \
                    if ((unsigned)yy < HH && (unsigned)xx < WW) {      \
                        float xv = __ldg(xi + (size_t)yy * WW + xx);   \
                        acc = fmaf(fmaf(xv, a2, beta), (w), acc);      \
                    }                                                  \
                }
                T(-1, -1, B00) T(-1, 0, B01) T(-1, 1, B02)
                T( 0, -1, B10) T( 0, 0, B11) T( 0, 1, B12)
                T( 1, -1, B20) T( 1, 0, B21) T( 1, 1, B22)
#undef T
                bo[(size_t)y * WW + gx] = fmaf(acc, 0.5f, K0C);
            }
        }
    }
}

// Row fetch: one aligned LDS.128 + warp shuffles for the halo floats.
// Lane 0 / lane 31 patch their outer halo column with a predicated scalar LDS.
__device__ __forceinline__ R6 ldrow(const float* p, int lane) {
    float4 m = *(const float4*)(p + 1);   // logical cols xb+1..xb+4 (16B-aligned)
    float lo = __shfl_up_sync(0xFFFFFFFFu, m.w, 1);     // col xb from lane-1
    float hi = __shfl_down_sync(0xFFFFFFFFu, m.x, 1);   // col xb+5 from lane+1
    if (lane == 0)  lo = p[0];    // logical col 0
    if (lane == 31) hi = p[5];    // logical col 129
    R6 r; r.v0 = lo; r.v1 = m.x; r.v2 = m.y; r.v3 = m.z; r.v4 = m.w; r.v5 = hi;
    return r;
}

// A is already saturated (frowZsat); edge tiles force padding value 0.5.
template <bool EDGE>
__device__ __forceinline__ void emit4(float* q, const float4& A, bool yok,
                                      bool x0, bool x1, bool x2, bool x3) {
    float4 o;
    if (EDGE) {
        o.x = (yok && x0) ? A.x : 0.5f;
        o.y = (yok && x1) ? A.y : 0.5f;
        o.z = (yok && x2) ? A.z : 0.5f;
        o.w = (yok && x3) ? A.w : 0.5f;
    } else {
        o = A;
    }
    *(float4*)q = o;
}

// Software-pipelined: prefetch row k+1's ldrow before emitting row k.
template <bool EDGE>
__device__ __forceinline__ float* do_steps(int nstep, float* a, float* b,
                                           const float4* BU, int lane,
                                           int o0, int xb, int gy0,
                                           bool x0, bool x1, bool x2, bool x3) {
#pragma unroll 1
    for (int t = 0; t < nstep; t++) {
        const float* ip = a + (o0 - 1) * SPW + xb + 3;
        float* op = b + o0 * SPW + xb + 4;
        float4 A0, A1, A2;
        R6 cur, nxt;
        cur = ldrow(ip, lane); ip += SPW;         // row o0-1
        nxt = ldrow(ip, lane); ip += SPW;         // row o0 (prefetched)
        A0 = BU[0]; frow<0, 0>(cur, A0);
        cur = nxt;
        nxt = ldrow(ip, lane); ip += SPW;         // prefetch row o0+1
        A1 = BU[1]; frow<1, 0>(cur, A0); frow<0, 0>(cur, A1);
#pragma unroll
        for (int k = 0; k < 6; k++) {             // consume rows o0+1 .. o0+6
            cur = nxt;
            nxt = ldrow(ip, lane); ip += SPW;     // prefetch rows o0+2 .. o0+7
            A2 = BU[2 + k];
            frowZsat(cur, A0);
            emit4<EDGE>(op + k * SPW, A0,
                        EDGE ? ((unsigned)(gy0 + o0 + k) < HH) : true,
                        x0, x1, x2, x3);
            frow<1, 0>(cur, A1); frow<0, 0>(cur, A2);
            A0 = A1; A1 = A2;
        }
        cur = nxt;
        nxt = ldrow(ip, lane);                    // prefetch row o0+8
        frowZsat(cur, A0);                        // consume row o0+7
        emit4<EDGE>(op + 6 * SPW, A0,
                    EDGE ? ((unsigned)(gy0 + o0 + 6) < HH) : true, x0, x1, x2, x3);
        frow<1, 0>(cur, A1);
        frowZsat(nxt, A1);                        // consume row o0+8
        emit4<EDGE>(op + 7 * SPW, A1,
                    EDGE ? ((unsigned)(gy0 + o0 + 7) < HH) : true, x0, x1, x2, x3);
        __syncthreads();
        float* tmp = a; a = b; b = tmp;
    }
    return a;   // final buffer
}

// PASS 0: u1 analytic -> 6 steps -> g_sA (u7)
// PASS 1: g_sA -> 7 steps -> g_sB (u14)
// PASS 2: g_sB -> 7 steps -> out  (u21)
template <int PASS>
__global__ void __launch_bounds__(NTH, 2) k_steps(float* __restrict__ out) {
    extern __shared__ float sm[];
    float* sA = sm;
    float* sB = sm + RH * SPW;
    const int tid = threadIdx.x, lane = tid & 31, wrp = tid >> 5;
    const int bx = blockIdx.x, by = blockIdx.y, img = blockIdx.z;
    const int gx0 = bx * TOX - 7, gy0 = by * TOY - 7;
    const bool edge = (bx == 0) | (bx == GX - 1) | (by == 0) | (by == GY - 1);

    const int o0 = 1 + 8 * wrp;     // update rows o0..o0+7 (1..96)
    const int xb = 4 * lane;        // update logical cols xb+1..xb+4 (1..128)

    // ---- BU2 into registers (rows o0..o0+7, cols xb+1..xb+4) ----
    float4 BU[8];
    {
        const float* bsrc = g_bu2 + (size_t)img * HW;
        if (!edge) {
#pragma unroll
            for (int j = 0; j < 8; j++) {
                const float2* p = (const float2*)(bsrc +
                    (size_t)(gy0 + o0 + j) * WW + (gx0 + 1 + xb));
                float2 u = __ldg(p), v = __ldg(p + 1);
                BU[j] = make_float4(u.x, u.y, v.x, v.y);
            }
        } else {
#pragma unroll
            for (int j = 0; j < 8; j++) {
                int gy = gy0 + o0 + j;
                float vv[4];
#pragma unroll
                for (int i = 0; i < 4; i++) {
                    int gx = gx0 + 1 + xb + i;
                    vv[i] = ((unsigned)gy < HH && (unsigned)gx < WW)
                              ? __ldg(bsrc + (size_t)gy * WW + gx) : 0.f;
                }
                BU[j] = make_float4(vv[0], vv[1], vv[2], vv[3]);
            }
        }
    }

    // ---- source region into sA ----
    if (PASS == 0) {
        const float* bsrc = g_bu2 + (size_t)img * HW;
        if (!edge) {
            for (int r = wrp; r < RH; r += NW) {
                const float* gp = bsrc + (size_t)(gy0 + r) * WW + gx0;
                float* sp = sA + r * SPW + 3;
                int c1 = 1 + 2 * lane, c2 = 65 + 2 * lane;
                float2 u = *(const float2*)(gp + c1);
                float2 v = *(const float2*)(gp + c2);
                u.x = __saturatef(S2K + u.x); u.y = __saturatef(S2K + u.y);
                v.x = __saturatef(S2K + v.x); v.y = __saturatef(S2K + v.y);
                *(float2*)(sp + c1) = u;
                *(float2*)(sp + c2) = v;
                if (lane == 0) {
                    sp[0]   = __saturatef(S2K + gp[0]);
                    sp[129] = __saturatef(S2K + gp[129]);
                }
            }
        } else {
            for (int r = wrp; r < RH; r += NW) {
                int gy = gy0 + r;
                bool yok = (unsigned)gy < HH;
                float* sp = sA + r * SPW + 3;
                for (int c = lane; c < RW; c += 32) {
                    int gx = gx0 + c;
                    sp[c] = (yok && (unsigned)gx < WW)
                              ? __saturatef(S2K + __ldg(bsrc + (size_t)gy * WW + gx))
                              : 0.5f;
                }
            }
        }
    } else {
        const float* src = (PASS == 1 ? g_sA : g_sB) + (size_t)img * HW;
        if (!edge) {
            for (int r = wrp; r < RH; r += NW) {
                const float* gp = src + (size_t)(gy0 + r) * WW + gx0;
                float* sp = sA + r * SPW + 3;
                int c1 = 1 + 2 * lane, c2 = 65 + 2 * lane;
                *(float2*)(sp + c1) = *(const float2*)(gp + c1);
                *(float2*)(sp + c2) = *(const float2*)(gp + c2);
                if (lane == 0) {
                    sp[0]   = gp[0];
                    sp[129] = gp[129];
                }
            }
        } else {
            for (int r = wrp; r < RH; r += NW) {
                int gy = gy0 + r;
                bool yok = (unsigned)gy < HH;
                float* sp = sA + r * SPW + 3;
                for (int c = lane; c < RW; c += 32) {
                    int gx = gx0 + c;
                    sp[c] = (yok && (unsigned)gx < WW)
                              ? __ldg(src + (size_t)gy * WW + gx) : 0.5f;
                }
            }
        }
    }
    __syncthreads();

    const bool x0 = (unsigned)(gx0 + xb + 1) < WW;
    const bool x1 = (unsigned)(gx0 + xb + 2) < WW;
    const bool x2 = (unsigned)(gx0 + xb + 3) < WW;
    const bool x3 = (unsigned)(gx0 + xb + 4) < WW;

    const int nstep = (PASS == 0) ? 6 : 7;
    float* fin = edge
        ? do_steps<true >(nstep, sA, sB, BU, lane, o0, xb, gy0, x0, x1, x2, x3)
        : do_steps<false>(nstep, sA, sB, BU, lane, o0, xb, gy0, true, true, true, true);

    // ---- writeback logical rows [7,90], cols [7,122] ----
    float* dst = (PASS == 0 ? g_sA : PASS == 1 ? g_sB : out) + (size_t)img * HW;
    if (!edge) {
        for (int r = 7 + wrp; r < 7 + TOY; r += NW) {
            float4* dp = (float4*)(dst + (size_t)(gy0 + r) * WW + gx0 + 7);
            const float* srow = fin + r * SPW + 10;   // logical col 7 -> phys 10
            if (lane < 29) {
                int c = 4 * lane;
                dp[lane] = make_float4(srow[c], srow[c+1], srow[c+2], srow[c+3]);
            }
        }
    } else {
        for (int r = 7 + wrp; r < 7 + TOY; r += NW) {
            int gy = gy0 + r;
            if ((unsigned)gy >= HH) continue;
            const float* srow = fin + r * SPW + 3;
            for (int c = 7 + lane; c < 7 + TOX; c += 32) {
                int gx = gx0 + c;
                if ((unsigned)gx < WW) dst[(size_t)gy * WW + gx] = srow[c];
            }
        }
    }
}

extern "C" void kernel_launch(void* const* d_in, const int* in_sizes, int n_in,
                              void* d_out, int out_size) {
    const float* x = (const float*)d_in[0];
    float* out = (float*)d_out;

    cudaFuncSetAttribute(k_steps<0>, cudaFuncAttributeMaxDynamicSharedMemorySize, SMEMB);
    cudaFuncSetAttribute(k_steps<1>, cudaFuncAttributeMaxDynamicSharedMemorySize, SMEMB);
    cudaFuncSetAttribute(k_steps<2>, cudaFuncAttributeMaxDynamicSharedMemorySize, SMEMB);

    k_init<<<1, 1>>>();
    k_minmax<<<2048, 256>>>((const float4*)x, (NB * HW) / 4);
    k_bu<<<dim3(1, HH / 2, NB), 256>>>(x);

    dim3 g(GX, GY, NB);
    k_steps<0><<<g, NTH, SMEMB>>>(out);
    k_steps<1><<<g, NTH, SMEMB>>>(out);
    k_steps<2><<<g, NTH, SMEMB>>>(out);
}